// round 1
// baseline (speedup 1.0000x reference)
#include <cuda_runtime.h>

#define N_AGENTS 16
#define NE_ 128
#define ED_ 96
#define HE_ 128
#define MD_ 32
#define NH_ 4
#define HD_ 32
#define NITEMS 1600
#define NTHREADS 256

// smem layout (float offsets)
#define OFF_X1   0          // X1: 128x128            (16384)
#define OFF_UN   16384      // X (128x96) then V (128x128) (16384)
#define OFF_QA   32768      // Q then attn: 16x128    (2048)
#define OFF_LOG  34816      // logits/weights 64x128, later x3 (8192)
#define OFF_KC   43008      // K chunk 32x132, later 'out' 16x128 (4224)
#define OFF_MASK 47232      // 128 entity-mask ints + allE flag
#define SMEM_FLOATS 47424
#define SMEM_BYTES (SMEM_FLOATS * 4)

__device__ int   g_mask_kind;           // 0=u8, 1=int32, 2=float32
__device__ float g_w1[NITEMS * N_AGENTS];
__device__ float g_v[NITEMS];

// ---------------------------------------------------------------------------
// Probe the dtype the harness used for the boolean entity_mask.
//  u8 bool  : 0/1 bytes at every position
//  int32    : byte==1 only at i%4==0
//  float32  : 1.0f -> byte 0x3F at i%4==3
// Scanning 64KB (>=16384 mask entries, ~15% true) makes misclassification
// probability ~0.
// ---------------------------------------------------------------------------
__global__ void detect_mask_kind_kernel(const unsigned char* __restrict__ m, int nbytes)
{
    __shared__ int fF32, fOdd;
    if (threadIdx.x == 0) { fF32 = 0; fOdd = 0; }
    __syncthreads();
    int lf = 0, lo = 0;
    for (int i = threadIdx.x; i < nbytes; i += blockDim.x) {
        unsigned char b = m[i];
        if (b != 0) {
            if ((i & 3) == 3 && b == 0x3F) lf = 1;
            if ((i & 3) != 0) lo = 1;
        }
    }
    if (lf) atomicOr(&fF32, 1);
    if (lo) atomicOr(&fOdd, 1);
    __syncthreads();
    if (threadIdx.x == 0)
        g_mask_kind = fF32 ? 2 : (fOdd ? 0 : 1);
}

// ---------------------------------------------------------------------------
// One CTA = one (batch item, hypernet). mode==0 -> w1 path, mode==1 -> v path.
// ---------------------------------------------------------------------------
__global__ void __launch_bounds__(NTHREADS)
hypernet_kernel(const float* __restrict__ ents,
                const void*  __restrict__ maskraw,
                const float* __restrict__ W1,  const float* __restrict__ B1,
                const float* __restrict__ WIN,
                const float* __restrict__ WOUT,const float* __restrict__ BOUT,
                const float* __restrict__ W2,  const float* __restrict__ B2,
                int mode)
{
    extern __shared__ float sm[];
    float* sX1  = sm + OFF_X1;
    float* sUN  = sm + OFF_UN;   // X, then V
    float* sQA  = sm + OFF_QA;   // Q, then attn
    float* sLog = sm + OFF_LOG;  // logits -> softmax weights -> x3
    float* sKc  = sm + OFF_KC;   // K chunk -> 'out'
    int*   mEnt = (int*)(sm + OFF_MASK);
    int*   mAll = mEnt + NE_;

    const int tid  = threadIdx.x;
    const int item = blockIdx.x;

    // ---- Phase A: load X (entities[item], 128x96) + masks ----------------
    {
        const float4* src = (const float4*)(ents + (size_t)item * NE_ * ED_);
        float4* dst = (float4*)sUN;
        #pragma unroll
        for (int i = 0; i < (NE_ * ED_ / 4) / NTHREADS; i++)
            dst[tid + i * NTHREADS] = src[tid + i * NTHREADS];

        if (tid < NE_) {
            int kind = g_mask_kind;
            long idx = (long)item * NE_ + tid;
            int mv;
            if (kind == 0)      mv = (((const unsigned char*)maskraw)[idx] != 0);
            else if (kind == 1) mv = (((const int*)maskraw)[idx] != 0);
            else                mv = (((const float*)maskraw)[idx] != 0.0f);
            mEnt[tid] = mv;
        }
    }
    __syncthreads();
    if (tid == 0) {
        int a = 1;
        for (int e = 0; e < NE_; e++) a &= mEnt[e];
        mAll[0] = a;
    }

    // ---- Phase B: X1 = relu(X @ W1 + B1)   (128x96 @ 96x128) -------------
    {
        const int r0 = (tid >> 4) * 8;
        const int c0 = (tid & 15) * 8;
        float acc[8][8];
        #pragma unroll
        for (int i = 0; i < 8; i++)
            #pragma unroll
            for (int j = 0; j < 8; j++) acc[i][j] = 0.f;

        float4 b0 = *(const float4*)(W1 + c0);
        float4 b1 = *(const float4*)(W1 + c0 + 4);
        for (int k = 0; k < ED_; k++) {
            float a[8];
            #pragma unroll
            for (int i = 0; i < 8; i++) a[i] = sUN[(r0 + i) * ED_ + k];
            int kn = (k + 1 < ED_) ? (k + 1) : k;
            float4 nb0 = *(const float4*)(W1 + kn * HE_ + c0);
            float4 nb1 = *(const float4*)(W1 + kn * HE_ + c0 + 4);
            float bb[8] = {b0.x, b0.y, b0.z, b0.w, b1.x, b1.y, b1.z, b1.w};
            #pragma unroll
            for (int i = 0; i < 8; i++)
                #pragma unroll
                for (int j = 0; j < 8; j++)
                    acc[i][j] = fmaf(a[i], bb[j], acc[i][j]);
            b0 = nb0; b1 = nb1;
        }
        float bias[8];
        #pragma unroll
        for (int j = 0; j < 8; j++) bias[j] = B1[c0 + j];
        #pragma unroll
        for (int i = 0; i < 8; i++)
            #pragma unroll
            for (int j = 0; j < 8; j++) {
                float v = acc[i][j] + bias[j];
                sX1[(r0 + i) * HE_ + c0 + j] = v > 0.f ? v : 0.f;
            }
    }
    __syncthreads();   // X1 ready; X (in sUN) is now dead

    // ---- Phase C: Q = (X1[0:16] @ WIN[:,0:128]) * rsqrt(HD) ---------------
    {
        const int q  = tid >> 4;
        const int c0 = (tid & 15) * 8;
        float acc[8] = {0, 0, 0, 0, 0, 0, 0, 0};
        #pragma unroll 2
        for (int k = 0; k < HE_; k++) {
            float a = sX1[q * HE_ + k];
            float4 w0 = *(const float4*)(WIN + k * (3 * HE_) + c0);
            float4 w1 = *(const float4*)(WIN + k * (3 * HE_) + c0 + 4);
            acc[0] = fmaf(a, w0.x, acc[0]); acc[1] = fmaf(a, w0.y, acc[1]);
            acc[2] = fmaf(a, w0.z, acc[2]); acc[3] = fmaf(a, w0.w, acc[3]);
            acc[4] = fmaf(a, w1.x, acc[4]); acc[5] = fmaf(a, w1.y, acc[5]);
            acc[6] = fmaf(a, w1.z, acc[6]); acc[7] = fmaf(a, w1.w, acc[7]);
        }
        const float scale = 0.17677669529663687f;  // 1/sqrt(32)
        #pragma unroll
        for (int j = 0; j < 8; j++) sQA[q * HE_ + c0 + j] = acc[j] * scale;
    }

    // ---- Phase D1: V = X1 @ WIN[:,256:384]  -> sUN ------------------------
    {
        const int r0 = (tid >> 4) * 8;
        const int c0 = (tid & 15) * 8;
        const float* WV = WIN + 2 * HE_;
        float acc[8][8];
        #pragma unroll
        for (int i = 0; i < 8; i++)
            #pragma unroll
            for (int j = 0; j < 8; j++) acc[i][j] = 0.f;

        float4 b0 = *(const float4*)(WV + c0);
        float4 b1 = *(const float4*)(WV + c0 + 4);
        for (int k = 0; k < HE_; k++) {
            float a[8];
            #pragma unroll
            for (int i = 0; i < 8; i++) a[i] = sX1[(r0 + i) * HE_ + k];
            int kn = (k + 1 < HE_) ? (k + 1) : k;
            float4 nb0 = *(const float4*)(WV + kn * (3 * HE_) + c0);
            float4 nb1 = *(const float4*)(WV + kn * (3 * HE_) + c0 + 4);
            float bb[8] = {b0.x, b0.y, b0.z, b0.w, b1.x, b1.y, b1.z, b1.w};
            #pragma unroll
            for (int i = 0; i < 8; i++)
                #pragma unroll
                for (int j = 0; j < 8; j++)
                    acc[i][j] = fmaf(a[i], bb[j], acc[i][j]);
            b0 = nb0; b1 = nb1;
        }
        #pragma unroll
        for (int i = 0; i < 8; i++)
            #pragma unroll
            for (int j = 0; j < 8; j++)
                sUN[(r0 + i) * HE_ + c0 + j] = acc[i][j];
    }

    // ---- Phase D2: K in 4 chunks of 32 entities + logits ------------------
    for (int ch = 0; ch < 4; ch++) {
        {   // K chunk: 32 rows x 128 cols
            const int row = tid >> 3;           // 0..31
            const int c0  = (tid & 7) * 16;
            const int e   = ch * 32 + row;
            const float* WK = WIN + HE_;
            float acc[16];
            #pragma unroll
            for (int j = 0; j < 16; j++) acc[j] = 0.f;
            #pragma unroll 2
            for (int k = 0; k < HE_; k++) {
                float a = sX1[e * HE_ + k];
                float4 w0 = *(const float4*)(WK + k * (3 * HE_) + c0);
                float4 w1 = *(const float4*)(WK + k * (3 * HE_) + c0 + 4);
                float4 w2 = *(const float4*)(WK + k * (3 * HE_) + c0 + 8);
                float4 w3 = *(const float4*)(WK + k * (3 * HE_) + c0 + 12);
                acc[0]  = fmaf(a, w0.x, acc[0]);  acc[1]  = fmaf(a, w0.y, acc[1]);
                acc[2]  = fmaf(a, w0.z, acc[2]);  acc[3]  = fmaf(a, w0.w, acc[3]);
                acc[4]  = fmaf(a, w1.x, acc[4]);  acc[5]  = fmaf(a, w1.y, acc[5]);
                acc[6]  = fmaf(a, w1.z, acc[6]);  acc[7]  = fmaf(a, w1.w, acc[7]);
                acc[8]  = fmaf(a, w2.x, acc[8]);  acc[9]  = fmaf(a, w2.y, acc[9]);
                acc[10] = fmaf(a, w2.z, acc[10]); acc[11] = fmaf(a, w2.w, acc[11]);
                acc[12] = fmaf(a, w3.x, acc[12]); acc[13] = fmaf(a, w3.y, acc[13]);
                acc[14] = fmaf(a, w3.z, acc[14]); acc[15] = fmaf(a, w3.w, acc[15]);
            }
            #pragma unroll
            for (int j = 0; j < 16; j += 4)
                *(float4*)(sKc + row * 132 + c0 + j) =
                    make_float4(acc[j], acc[j + 1], acc[j + 2], acc[j + 3]);
        }
        __syncthreads();
        {   // logits for this chunk: 4 heads x 16 q x 32 e
            const int pair = tid >> 2;          // h*16+q, 0..63
            const int h = pair >> 4, q = pair & 15;
            const int e0 = (tid & 3) * 8;
            float acc[8] = {0, 0, 0, 0, 0, 0, 0, 0};
            #pragma unroll 4
            for (int d = 0; d < HD_; d++) {
                float qv = sQA[q * HE_ + h * HD_ + d];
                #pragma unroll
                for (int j = 0; j < 8; j++)
                    acc[j] = fmaf(qv, sKc[(e0 + j) * 132 + h * HD_ + d], acc[j]);
            }
            #pragma unroll
            for (int j = 0; j < 8; j++)
                sLog[pair * NE_ + ch * 32 + e0 + j] = acc[j];
        }
        __syncthreads();
    }

    // ---- Softmax over entities, with pre-mask and all_masked zeroing ------
    {
        const int warp = tid >> 5, lane = tid & 31;
        const int allE = mAll[0];
        for (int r = warp; r < NH_ * N_AGENTS; r += 8) {
            const int q  = r & 15;
            const int qm = mEnt[q];
            float v[4];
            #pragma unroll
            for (int i = 0; i < 4; i++) {
                int e = lane + 32 * i;
                v[i] = (qm | mEnt[e]) ? -1e9f : sLog[r * NE_ + e];
            }
            float mx = fmaxf(fmaxf(v[0], v[1]), fmaxf(v[2], v[3]));
            #pragma unroll
            for (int o = 16; o > 0; o >>= 1)
                mx = fmaxf(mx, __shfl_xor_sync(0xffffffffu, mx, o));
            float ex[4], s = 0.f;
            #pragma unroll
            for (int i = 0; i < 4; i++) { ex[i] = __expf(v[i] - mx); s += ex[i]; }
            #pragma unroll
            for (int o = 16; o > 0; o >>= 1)
                s += __shfl_xor_sync(0xffffffffu, s, o);
            const float inv = (qm | allE) ? 0.f : (1.f / s);
            #pragma unroll
            for (int i = 0; i < 4; i++)
                sLog[r * NE_ + lane + 32 * i] = ex[i] * inv;
        }
    }
    __syncthreads();

    // ---- Phase E: attn[q, h*32+d] = sum_e w[h,q,e] * V[e, h*32+d] -> sQA --
    {
        const int q  = tid >> 4;
        const int c0 = (tid & 15) * 8;
        const int h  = c0 >> 5;
        const float* wrow = sLog + (h * 16 + q) * NE_;
        float acc[8] = {0, 0, 0, 0, 0, 0, 0, 0};
        #pragma unroll 2
        for (int e = 0; e < NE_; e++) {
            float wv = wrow[e];
            float4 v0 = *(const float4*)(sUN + e * HE_ + c0);
            float4 v1 = *(const float4*)(sUN + e * HE_ + c0 + 4);
            acc[0] = fmaf(wv, v0.x, acc[0]); acc[1] = fmaf(wv, v0.y, acc[1]);
            acc[2] = fmaf(wv, v0.z, acc[2]); acc[3] = fmaf(wv, v0.w, acc[3]);
            acc[4] = fmaf(wv, v1.x, acc[4]); acc[5] = fmaf(wv, v1.y, acc[5]);
            acc[6] = fmaf(wv, v1.z, acc[6]); acc[7] = fmaf(wv, v1.w, acc[7]);
        }
        #pragma unroll
        for (int j = 0; j < 8; j++) sQA[q * HE_ + c0 + j] = acc[j];
    }
    __syncthreads();

    // ---- Phase F: out = attn @ WOUT + BOUT, zero masked agents -> sKc -----
    {
        const int q  = tid >> 4;
        const int c0 = (tid & 15) * 8;
        float acc[8] = {0, 0, 0, 0, 0, 0, 0, 0};
        #pragma unroll 2
        for (int k = 0; k < HE_; k++) {
            float a = sQA[q * HE_ + k];
            float4 w0 = *(const float4*)(WOUT + k * HE_ + c0);
            float4 w1 = *(const float4*)(WOUT + k * HE_ + c0 + 4);
            acc[0] = fmaf(a, w0.x, acc[0]); acc[1] = fmaf(a, w0.y, acc[1]);
            acc[2] = fmaf(a, w0.z, acc[2]); acc[3] = fmaf(a, w0.w, acc[3]);
            acc[4] = fmaf(a, w1.x, acc[4]); acc[5] = fmaf(a, w1.y, acc[5]);
            acc[6] = fmaf(a, w1.z, acc[6]); acc[7] = fmaf(a, w1.w, acc[7]);
        }
        const int qm = mEnt[q];
        #pragma unroll
        for (int j = 0; j < 8; j++)
            sKc[q * HE_ + c0 + j] = qm ? 0.f : (acc[j] + BOUT[c0 + j]);
    }
    __syncthreads();

    // ---- Phase G: x3 = out @ W2 + B2, zero masked, then reduce ------------
    {
        const int q = tid >> 4;
        const int c = (tid & 15) * 2;
        float s0 = 0.f, s1 = 0.f;
        #pragma unroll 2
        for (int k = 0; k < HE_; k++) {
            float a = sKc[q * HE_ + k];
            s0 = fmaf(a, W2[k * MD_ + c], s0);
            s1 = fmaf(a, W2[k * MD_ + c + 1], s1);
        }
        s0 += B2[c]; s1 += B2[c + 1];
        if (mEnt[q]) { s0 = 0.f; s1 = 0.f; }
        sLog[q * MD_ + c]     = s0;
        sLog[q * MD_ + c + 1] = s1;
    }
    __syncthreads();

    if (mode == 0) {
        if (tid < N_AGENTS) {
            float s = 0.f;
            #pragma unroll
            for (int mcol = 0; mcol < MD_; mcol++) s += sLog[tid * MD_ + mcol];
            g_w1[item * N_AGENTS + tid] = s * (1.f / MD_);
        }
    } else {
        if (tid == 0) {
            float s = 0.f;
            for (int i = 0; i < N_AGENTS * MD_; i++) s += sLog[i];
            g_v[item] = s * (1.f / (N_AGENTS * MD_));
        }
    }
}

// ---------------------------------------------------------------------------
// q_tot[i] = sum_a qs[i,a] * |w1[i,a]| + v[i]
// ---------------------------------------------------------------------------
__global__ void finalize_kernel(const float* __restrict__ qs, float* __restrict__ out)
{
    int i = blockIdx.x * blockDim.x + threadIdx.x;
    if (i < NITEMS) {
        float s = 0.f;
        #pragma unroll
        for (int a = 0; a < N_AGENTS; a++)
            s = fmaf(qs[i * N_AGENTS + a], fabsf(g_w1[i * N_AGENTS + a]), s);
        out[i] = s + g_v[i];
    }
}

extern "C" void kernel_launch(void* const* d_in, const int* in_sizes, int n_in,
                              void* d_out, int out_size)
{
    const float* qs   = (const float*)d_in[0];
    const float* ents = (const float*)d_in[1];
    const void*  mask = d_in[2];

    const float* w1_fc1_w = (const float*)d_in[3];
    const float* w1_fc1_b = (const float*)d_in[4];
    const float* w1_in_w  = (const float*)d_in[5];
    const float* w1_out_w = (const float*)d_in[6];
    const float* w1_out_b = (const float*)d_in[7];
    const float* w1_fc2_w = (const float*)d_in[8];
    const float* w1_fc2_b = (const float*)d_in[9];

    const float* v_fc1_w  = (const float*)d_in[10];
    const float* v_fc1_b  = (const float*)d_in[11];
    const float* v_in_w   = (const float*)d_in[12];
    const float* v_out_w  = (const float*)d_in[13];
    const float* v_out_b  = (const float*)d_in[14];
    const float* v_fc2_w  = (const float*)d_in[15];
    const float* v_fc2_b  = (const float*)d_in[16];

    cudaFuncSetAttribute(hypernet_kernel,
                         cudaFuncAttributeMaxDynamicSharedMemorySize, SMEM_BYTES);

    detect_mask_kind_kernel<<<1, 256>>>((const unsigned char*)mask, 65536);

    hypernet_kernel<<<NITEMS, NTHREADS, SMEM_BYTES>>>(
        ents, mask, w1_fc1_w, w1_fc1_b, w1_in_w, w1_out_w, w1_out_b,
        w1_fc2_w, w1_fc2_b, 0);

    hypernet_kernel<<<NITEMS, NTHREADS, SMEM_BYTES>>>(
        ents, mask, v_fc1_w, v_fc1_b, v_in_w, v_out_w, v_out_b,
        v_fc2_w, v_fc2_b, 1);

    finalize_kernel<<<(NITEMS + 255) / 256, 256>>>(qs, (float*)d_out);
}

// round 2
// speedup vs baseline: 2.7078x; 2.7078x over previous
#include <cuda_runtime.h>

#define N_AGENTS 16
#define NE_ 128
#define ED_ 96
#define HE_ 128
#define MD_ 32
#define NH_ 4
#define HD_ 32
#define NITEMS 1600
#define NTHREADS 256

// smem layout (float offsets)
#define OFF_X1   0          // X1: 128x128                      (16384)
#define OFF_V    16384      // X (128x96) then V (128x128)      (16384)
#define OFF_LOG  32768      // logits -> softmax w -> x3        (8192)
#define OFF_QA   40960      // Q then attn: 16x128              (2048)
#define OFF_KC   43008      // K slab 32x132, later 'out' 16x128(4224)
#define OFF_WS   47232      // weight staging: 2 x 4096 floats  (8192)
#define OFF_MASK 55424      // 128 entity-mask ints + allE flag
#define SMEM_FLOATS 55560
#define SMEM_BYTES (SMEM_FLOATS * 4)

__device__ int   g_mask_kind;           // 0=u8, 1=int32, 2=float32
__device__ float g_w1[NITEMS * N_AGENTS];
__device__ float g_v[NITEMS];

// ---------------------------------------------------------------------------
__global__ void detect_mask_kind_kernel(const unsigned char* __restrict__ m, int nbytes)
{
    __shared__ int fF32, fOdd;
    if (threadIdx.x == 0) { fF32 = 0; fOdd = 0; }
    __syncthreads();
    int lf = 0, lo = 0;
    for (int i = threadIdx.x; i < nbytes; i += blockDim.x) {
        unsigned char b = m[i];
        if (b != 0) {
            if ((i & 3) == 3 && b == 0x3F) lf = 1;
            if ((i & 3) != 0) lo = 1;
        }
    }
    if (lf) atomicOr(&fF32, 1);
    if (lo) atomicOr(&fOdd, 1);
    __syncthreads();
    if (threadIdx.x == 0)
        g_mask_kind = fF32 ? 2 : (fOdd ? 0 : 1);
}

// ---------------------------------------------------------------------------
// Weight staging: one chunk = 32 k-rows x 128 cols = 4096 floats = 1024 float4
// (4 float4 per thread). Coalesced global read, conflict-free smem store.
// ---------------------------------------------------------------------------
__device__ __forceinline__ void stage_load(float4 pf[4], const float* __restrict__ W,
                                           int k0, int ldw, int tid)
{
    #pragma unroll
    for (int i = 0; i < 4; i++) {
        int q = tid + i * 256;
        int kr = q >> 5, c4 = q & 31;
        pf[i] = *(const float4*)(W + (size_t)(k0 + kr) * ldw + c4 * 4);
    }
}
__device__ __forceinline__ void stage_store(float* buf, const float4 pf[4], int tid)
{
    #pragma unroll
    for (int i = 0; i < 4; i++)
        ((float4*)buf)[tid + i * 256] = pf[i];
}

// ---------------------------------------------------------------------------
// One CTA = one (item, hypernet). blockIdx.x = item, blockIdx.y = mode.
// ---------------------------------------------------------------------------
__global__ void __launch_bounds__(NTHREADS)
hypernet_kernel(const float* __restrict__ ents,
                const void*  __restrict__ maskraw,
                const float* __restrict__ W1a,  const float* __restrict__ B1a,
                const float* __restrict__ WINa,
                const float* __restrict__ WOUTa,const float* __restrict__ BOUTa,
                const float* __restrict__ W2a,  const float* __restrict__ B2a,
                const float* __restrict__ W1b,  const float* __restrict__ B1b,
                const float* __restrict__ WINb,
                const float* __restrict__ WOUTb,const float* __restrict__ BOUTb,
                const float* __restrict__ W2b,  const float* __restrict__ B2b)
{
    extern __shared__ float sm[];
    float* sX1  = sm + OFF_X1;
    float* sV   = sm + OFF_V;    // X, then V
    float* sLog = sm + OFF_LOG;
    float* sQA  = sm + OFF_QA;
    float* sKc  = sm + OFF_KC;
    float* sWs  = sm + OFF_WS;   // 2 x 4096
    int*   mEnt = (int*)(sm + OFF_MASK);
    int*   mAll = mEnt + NE_;

    const int tid  = threadIdx.x;
    const int item = blockIdx.x;
    const int mode = blockIdx.y;

    const float* W1   = mode ? W1b   : W1a;
    const float* B1   = mode ? B1b   : B1a;
    const float* WIN  = mode ? WINb  : WINa;
    const float* WOUT = mode ? WOUTb : WOUTa;
    const float* BOUT = mode ? BOUTb : BOUTa;
    const float* W2   = mode ? W2b   : W2a;
    const float* B2   = mode ? B2b   : B2a;

    // common tile indices
    const int r0  = (tid >> 4) * 8;          // 8x8-tile row
    const int c0  = (tid & 15) * 8;          // 8x8-tile col (and 1x8 col)
    const int qrow = tid >> 4;               // 1x8 row (0..15)

    // ---- Phase A: load X (128x96) + masks ---------------------------------
    {
        const float4* src = (const float4*)(ents + (size_t)item * NE_ * ED_);
        float4* dst = (float4*)sV;
        #pragma unroll
        for (int i = 0; i < (NE_ * ED_ / 4) / NTHREADS; i++)
            dst[tid + i * NTHREADS] = src[tid + i * NTHREADS];

        if (tid < NE_) {
            int kind = g_mask_kind;
            long idx = (long)item * NE_ + tid;
            int mv;
            if (kind == 0)      mv = (((const unsigned char*)maskraw)[idx] != 0);
            else if (kind == 1) mv = (((const int*)maskraw)[idx] != 0);
            else                mv = (((const float*)maskraw)[idx] != 0.0f);
            mEnt[tid] = mv;
        }
    }
    __syncthreads();
    if (tid == 0) {
        int a = 1;
        for (int e = 0; e < NE_; e++) a &= mEnt[e];
        mAll[0] = a;
    }

    // ---- Phase B: X1 = relu(X @ W1 + B1)  (staged W1, 3 chunks of 32k) ----
    {
        float acc[8][8];
        #pragma unroll
        for (int i = 0; i < 8; i++)
            #pragma unroll
            for (int j = 0; j < 8; j++) acc[i][j] = 0.f;

        float4 pf[4];
        stage_load(pf, W1, 0, HE_, tid);
        stage_store(sWs, pf, tid);
        __syncthreads();

        for (int ch = 0; ch < 3; ch++) {
            if (ch < 2) stage_load(pf, W1, (ch + 1) * 32, HE_, tid);
            const float* buf = sWs + (ch & 1) * 4096;
            const int kb = ch * 32;
            #pragma unroll 4
            for (int kk = 0; kk < 32; kk++) {
                float a[8];
                #pragma unroll
                for (int i = 0; i < 8; i++) a[i] = sV[(r0 + i) * ED_ + kb + kk];
                float4 b0 = *(const float4*)(buf + kk * 128 + c0);
                float4 b1 = *(const float4*)(buf + kk * 128 + c0 + 4);
                float bb[8] = {b0.x, b0.y, b0.z, b0.w, b1.x, b1.y, b1.z, b1.w};
                #pragma unroll
                for (int i = 0; i < 8; i++)
                    #pragma unroll
                    for (int j = 0; j < 8; j++)
                        acc[i][j] = fmaf(a[i], bb[j], acc[i][j]);
            }
            if (ch < 2) stage_store(sWs + ((ch + 1) & 1) * 4096, pf, tid);
            __syncthreads();
        }

        float bias[8];
        #pragma unroll
        for (int j = 0; j < 8; j++) bias[j] = B1[c0 + j];
        #pragma unroll
        for (int i = 0; i < 8; i++)
            #pragma unroll
            for (int j = 0; j < 8; j++) {
                float v = acc[i][j] + bias[j];
                sX1[(r0 + i) * HE_ + c0 + j] = v > 0.f ? v : 0.f;
            }
    }
    __syncthreads();   // X1 ready; X (sV) dead

    // ---- Phase C: Q = (X1[0:16] @ WIN[:,0:128]) * rsqrt(HD)  (staged) -----
    {
        float acc[8] = {0, 0, 0, 0, 0, 0, 0, 0};
        float4 pf[4];
        stage_load(pf, WIN, 0, 3 * HE_, tid);
        stage_store(sWs, pf, tid);
        __syncthreads();

        for (int ch = 0; ch < 4; ch++) {
            if (ch < 3) stage_load(pf, WIN, (ch + 1) * 32, 3 * HE_, tid);
            const float* buf = sWs + (ch & 1) * 4096;
            const int kb = ch * 32;
            #pragma unroll 4
            for (int kk = 0; kk < 32; kk++) {
                float a = sX1[qrow * HE_ + kb + kk];
                float4 b0 = *(const float4*)(buf + kk * 128 + c0);
                float4 b1 = *(const float4*)(buf + kk * 128 + c0 + 4);
                acc[0] = fmaf(a, b0.x, acc[0]); acc[1] = fmaf(a, b0.y, acc[1]);
                acc[2] = fmaf(a, b0.z, acc[2]); acc[3] = fmaf(a, b0.w, acc[3]);
                acc[4] = fmaf(a, b1.x, acc[4]); acc[5] = fmaf(a, b1.y, acc[5]);
                acc[6] = fmaf(a, b1.z, acc[6]); acc[7] = fmaf(a, b1.w, acc[7]);
            }
            if (ch < 3) stage_store(sWs + ((ch + 1) & 1) * 4096, pf, tid);
            __syncthreads();
        }
        const float scale = 0.17677669529663687f;  // 1/sqrt(32)
        #pragma unroll
        for (int j = 0; j < 8; j++) sQA[qrow * HE_ + c0 + j] = acc[j] * scale;
    }

    // ---- Phase D1: V = X1 @ WIN[:,256:384] -> sV  (staged) ----------------
    {
        float acc[8][8];
        #pragma unroll
        for (int i = 0; i < 8; i++)
            #pragma unroll
            for (int j = 0; j < 8; j++) acc[i][j] = 0.f;

        const float* WV = WIN + 2 * HE_;
        float4 pf[4];
        stage_load(pf, WV, 0, 3 * HE_, tid);
        stage_store(sWs, pf, tid);
        __syncthreads();

        for (int ch = 0; ch < 4; ch++) {
            if (ch < 3) stage_load(pf, WV, (ch + 1) * 32, 3 * HE_, tid);
            const float* buf = sWs + (ch & 1) * 4096;
            const int kb = ch * 32;
            #pragma unroll 4
            for (int kk = 0; kk < 32; kk++) {
                float a[8];
                #pragma unroll
                for (int i = 0; i < 8; i++) a[i] = sX1[(r0 + i) * HE_ + kb + kk];
                float4 b0 = *(const float4*)(buf + kk * 128 + c0);
                float4 b1 = *(const float4*)(buf + kk * 128 + c0 + 4);
                float bb[8] = {b0.x, b0.y, b0.z, b0.w, b1.x, b1.y, b1.z, b1.w};
                #pragma unroll
                for (int i = 0; i < 8; i++)
                    #pragma unroll
                    for (int j = 0; j < 8; j++)
                        acc[i][j] = fmaf(a[i], bb[j], acc[i][j]);
            }
            if (ch < 3) stage_store(sWs + ((ch + 1) & 1) * 4096, pf, tid);
            __syncthreads();
        }
        #pragma unroll
        for (int i = 0; i < 8; i++)
            #pragma unroll
            for (int j = 0; j < 8; j++)
                sV[(r0 + i) * HE_ + c0 + j] = acc[i][j];
    }

    // ---- Phase D2: K fully in registers (staged WK), then slab->logits ----
    {
        float acc[8][8];
        #pragma unroll
        for (int i = 0; i < 8; i++)
            #pragma unroll
            for (int j = 0; j < 8; j++) acc[i][j] = 0.f;

        const float* WK = WIN + HE_;
        float4 pf[4];
        stage_load(pf, WK, 0, 3 * HE_, tid);
        __syncthreads();               // all reads of sWs (phase D1) done
        stage_store(sWs, pf, tid);
        __syncthreads();

        for (int ch = 0; ch < 4; ch++) {
            if (ch < 3) stage_load(pf, WK, (ch + 1) * 32, 3 * HE_, tid);
            const float* buf = sWs + (ch & 1) * 4096;
            const int kb = ch * 32;
            #pragma unroll 4
            for (int kk = 0; kk < 32; kk++) {
                float a[8];
                #pragma unroll
                for (int i = 0; i < 8; i++) a[i] = sX1[(r0 + i) * HE_ + kb + kk];
                float4 b0 = *(const float4*)(buf + kk * 128 + c0);
                float4 b1 = *(const float4*)(buf + kk * 128 + c0 + 4);
                float bb[8] = {b0.x, b0.y, b0.z, b0.w, b1.x, b1.y, b1.z, b1.w};
                #pragma unroll
                for (int i = 0; i < 8; i++)
                    #pragma unroll
                    for (int j = 0; j < 8; j++)
                        acc[i][j] = fmaf(a[i], bb[j], acc[i][j]);
            }
            if (ch < 3) stage_store(sWs + ((ch + 1) & 1) * 4096, pf, tid);
            __syncthreads();
        }

        // dump K in 32-entity slabs + compute logits for each slab
        for (int ech = 0; ech < 4; ech++) {
            if (r0 >= ech * 32 && r0 < (ech + 1) * 32) {
                const int rr = r0 - ech * 32;
                #pragma unroll
                for (int i = 0; i < 8; i++)
                    #pragma unroll
                    for (int j = 0; j < 8; j += 4)
                        *(float4*)(sKc + (rr + i) * 132 + c0 + j) =
                            make_float4(acc[i][j], acc[i][j+1], acc[i][j+2], acc[i][j+3]);
            }
            __syncthreads();
            {   // logits: 4 heads x 16 q x 32 e
                const int pair = tid >> 2;          // h*16+q
                const int h = pair >> 4, q = pair & 15;
                const int e0 = (tid & 3) * 8;
                float lg[8] = {0, 0, 0, 0, 0, 0, 0, 0};
                #pragma unroll 4
                for (int d = 0; d < HD_; d++) {
                    float qv = sQA[q * HE_ + h * HD_ + d];
                    #pragma unroll
                    for (int j = 0; j < 8; j++)
                        lg[j] = fmaf(qv, sKc[(e0 + j) * 132 + h * HD_ + d], lg[j]);
                }
                #pragma unroll
                for (int j = 0; j < 8; j++)
                    sLog[pair * NE_ + ech * 32 + e0 + j] = lg[j];
            }
            __syncthreads();
        }
    }

    // ---- Softmax ----------------------------------------------------------
    {
        const int warp = tid >> 5, lane = tid & 31;
        const int allE = mAll[0];
        for (int r = warp; r < NH_ * N_AGENTS; r += 8) {
            const int q  = r & 15;
            const int qm = mEnt[q];
            float v[4];
            #pragma unroll
            for (int i = 0; i < 4; i++) {
                int e = lane + 32 * i;
                v[i] = (qm | mEnt[e]) ? -1e9f : sLog[r * NE_ + e];
            }
            float mx = fmaxf(fmaxf(v[0], v[1]), fmaxf(v[2], v[3]));
            #pragma unroll
            for (int o = 16; o > 0; o >>= 1)
                mx = fmaxf(mx, __shfl_xor_sync(0xffffffffu, mx, o));
            float ex[4], s = 0.f;
            #pragma unroll
            for (int i = 0; i < 4; i++) { ex[i] = __expf(v[i] - mx); s += ex[i]; }
            #pragma unroll
            for (int o = 16; o > 0; o >>= 1)
                s += __shfl_xor_sync(0xffffffffu, s, o);
            const float inv = (qm | allE) ? 0.f : (1.f / s);
            #pragma unroll
            for (int i = 0; i < 4; i++)
                sLog[r * NE_ + lane + 32 * i] = ex[i] * inv;
        }
    }
    __syncthreads();

    // ---- Phase E: attn = w @ V -> sQA (all smem) ---------------------------
    {
        const int h = c0 >> 5;
        const float* wrow = sLog + (h * 16 + qrow) * NE_;
        float acc[8] = {0, 0, 0, 0, 0, 0, 0, 0};
        #pragma unroll 2
        for (int e = 0; e < NE_; e++) {
            float wv = wrow[e];
            float4 v0 = *(const float4*)(sV + e * HE_ + c0);
            float4 v1 = *(const float4*)(sV + e * HE_ + c0 + 4);
            acc[0] = fmaf(wv, v0.x, acc[0]); acc[1] = fmaf(wv, v0.y, acc[1]);
            acc[2] = fmaf(wv, v0.z, acc[2]); acc[3] = fmaf(wv, v0.w, acc[3]);
            acc[4] = fmaf(wv, v1.x, acc[4]); acc[5] = fmaf(wv, v1.y, acc[5]);
            acc[6] = fmaf(wv, v1.z, acc[6]); acc[7] = fmaf(wv, v1.w, acc[7]);
        }
        __syncthreads();   // sQA (Q) fully consumed
        #pragma unroll
        for (int j = 0; j < 8; j++) sQA[qrow * HE_ + c0 + j] = acc[j];
    }
    __syncthreads();

    // ---- Phase F: out = attn @ WOUT + BOUT (staged) -> sKc -----------------
    {
        float acc[8] = {0, 0, 0, 0, 0, 0, 0, 0};
        float4 pf[4];
        stage_load(pf, WOUT, 0, HE_, tid);
        stage_store(sWs, pf, tid);
        __syncthreads();

        for (int ch = 0; ch < 4; ch++) {
            if (ch < 3) stage_load(pf, WOUT, (ch + 1) * 32, HE_, tid);
            const float* buf = sWs + (ch & 1) * 4096;
            const int kb = ch * 32;
            #pragma unroll 4
            for (int kk = 0; kk < 32; kk++) {
                float a = sQA[qrow * HE_ + kb + kk];
                float4 b0 = *(const float4*)(buf + kk * 128 + c0);
                float4 b1 = *(const float4*)(buf + kk * 128 + c0 + 4);
                acc[0] = fmaf(a, b0.x, acc[0]); acc[1] = fmaf(a, b0.y, acc[1]);
                acc[2] = fmaf(a, b0.z, acc[2]); acc[3] = fmaf(a, b0.w, acc[3]);
                acc[4] = fmaf(a, b1.x, acc[4]); acc[5] = fmaf(a, b1.y, acc[5]);
                acc[6] = fmaf(a, b1.z, acc[6]); acc[7] = fmaf(a, b1.w, acc[7]);
            }
            if (ch < 3) stage_store(sWs + ((ch + 1) & 1) * 4096, pf, tid);
            __syncthreads();
        }
        const int qm = mEnt[qrow];
        #pragma unroll
        for (int j = 0; j < 8; j++)
            sKc[qrow * HE_ + c0 + j] = qm ? 0.f : (acc[j] + BOUT[c0 + j]);
    }
    __syncthreads();

    // ---- Phase G: x3 = out @ W2 + B2, zero masked, reduce ------------------
    {
        // stage all of W2 (128x32 = 4096 floats) once
        float4 pf[4];
        #pragma unroll
        for (int i = 0; i < 4; i++)
            pf[i] = ((const float4*)W2)[tid + i * 256];
        stage_store(sWs, pf, tid);
        __syncthreads();

        const int c = (tid & 15) * 2;
        float s0 = 0.f, s1 = 0.f;
        #pragma unroll 4
        for (int k = 0; k < HE_; k++) {
            float a = sKc[qrow * HE_ + k];
            s0 = fmaf(a, sWs[k * MD_ + c], s0);
            s1 = fmaf(a, sWs[k * MD_ + c + 1], s1);
        }
        s0 += B2[c]; s1 += B2[c + 1];
        if (mEnt[qrow]) { s0 = 0.f; s1 = 0.f; }
        sLog[qrow * MD_ + c]     = s0;
        sLog[qrow * MD_ + c + 1] = s1;
    }
    __syncthreads();

    if (mode == 0) {
        if (tid < N_AGENTS) {
            float s = 0.f;
            #pragma unroll
            for (int mcol = 0; mcol < MD_; mcol++) s += sLog[tid * MD_ + mcol];
            g_w1[item * N_AGENTS + tid] = s * (1.f / MD_);
        }
    } else {
        if (tid == 0) {
            float s = 0.f;
            for (int i = 0; i < N_AGENTS * MD_; i++) s += sLog[i];
            g_v[item] = s * (1.f / (N_AGENTS * MD_));
        }
    }
}

// ---------------------------------------------------------------------------
__global__ void finalize_kernel(const float* __restrict__ qs, float* __restrict__ out)
{
    int i = blockIdx.x * blockDim.x + threadIdx.x;
    if (i < NITEMS) {
        float s = 0.f;
        #pragma unroll
        for (int a = 0; a < N_AGENTS; a++)
            s = fmaf(qs[i * N_AGENTS + a], fabsf(g_w1[i * N_AGENTS + a]), s);
        out[i] = s + g_v[i];
    }
}

extern "C" void kernel_launch(void* const* d_in, const int* in_sizes, int n_in,
                              void* d_out, int out_size)
{
    const float* qs   = (const float*)d_in[0];
    const float* ents = (const float*)d_in[1];
    const void*  mask = d_in[2];

    cudaFuncSetAttribute(hypernet_kernel,
                         cudaFuncAttributeMaxDynamicSharedMemorySize, SMEM_BYTES);

    detect_mask_kind_kernel<<<1, 256>>>((const unsigned char*)mask, 65536);

    dim3 grid(NITEMS, 2);
    hypernet_kernel<<<grid, NTHREADS, SMEM_BYTES>>>(
        ents, mask,
        (const float*)d_in[3],  (const float*)d_in[4],  (const float*)d_in[5],
        (const float*)d_in[6],  (const float*)d_in[7],  (const float*)d_in[8],
        (const float*)d_in[9],
        (const float*)d_in[10], (const float*)d_in[11], (const float*)d_in[12],
        (const float*)d_in[13], (const float*)d_in[14], (const float*)d_in[15],
        (const float*)d_in[16]);

    finalize_kernel<<<(NITEMS + 255) / 256, 256>>>(qs, (float*)d_out);
}